// round 6
// baseline (speedup 1.0000x reference)
#include <cuda_runtime.h>
#include <cuda_bf16.h>
#include <math.h>
#include <stdint.h>

#define NUM_NODES 262144
#define HID 256
#define NGRAPH 1024
#define NTILES (NUM_NODES / 128)   // 2048
#define NSM 148

// ---------------- scratch (static device globals) ----------------
__device__ float g_s[NUM_NODES];   // scores, then weights
__device__ float g_m[NGRAPH];      // segment max
__device__ float g_sw[NGRAPH];     // segment sum of exp
// W1^T packed b-frags: [kstep 0..15][nt 0..15][lane 0..31][bh0,bh1,bl0,bl1]
__device__ uint32_t g_B[16 * 16 * 32 * 4];   // 32768 u32 = 128KB

__device__ __forceinline__ void atomicMaxF(float* addr, float val) {
    if (val >= 0.f) atomicMax((int*)addr, __float_as_int(val));
    else            atomicMin((unsigned int*)addr, __float_as_uint(val));
}
__device__ __forceinline__ uint32_t smem_u32(const void* p) {
    uint32_t a;
    asm("{ .reg .u64 t; cvta.to.shared.u64 t, %1; cvt.u32.u64 %0, t; }" : "=r"(a) : "l"(p));
    return a;
}
__device__ __forceinline__ void mma_bf16(float* c, const uint32_t* a,
                                         uint32_t b0, uint32_t b1) {
    asm volatile(
        "mma.sync.aligned.m16n8k16.row.col.f32.bf16.bf16.f32 "
        "{%0,%1,%2,%3}, {%4,%5,%6,%7}, {%8,%9}, {%0,%1,%2,%3};"
        : "+f"(c[0]), "+f"(c[1]), "+f"(c[2]), "+f"(c[3])
        : "r"(a[0]), "r"(a[1]), "r"(a[2]), "r"(a[3]), "r"(b0), "r"(b1));
}
__device__ __forceinline__ void ldsm_x4(uint32_t* a, uint32_t addr) {
    asm volatile("ldmatrix.sync.aligned.m8n8.x4.shared.b16 {%0,%1,%2,%3}, [%4];"
        : "=r"(a[0]), "=r"(a[1]), "=r"(a[2]), "=r"(a[3]) : "r"(addr));
}

// ---------------- prep: W1^T -> packed split-bf16 b-frag quads -------------
__global__ void prep_kernel(const float* __restrict__ W1) {  // W1[256][128]
    int i = blockIdx.x * 256 + threadIdx.x;   // 0..8191
    if (i >= 8192) return;
    int l = i & 31, nt = (i >> 5) & 15, ks = i >> 9;   // kstep 0..15
    int gr = l >> 2, qc = l & 3;
    int n = nt * 8 + gr;
    int kp0 = (ks >> 2) * 32 + (ks & 3) * 8 + qc;      // k-pair indices
    int kp1 = kp0 + 4;
    float w00 = W1[(2 * kp0) * 128 + n],     w01 = W1[(2 * kp0 + 1) * 128 + n];
    float w10 = W1[(2 * kp1) * 128 + n],     w11 = W1[(2 * kp1 + 1) * 128 + n];
    __nv_bfloat16 h00 = __float2bfloat16(w00), h01 = __float2bfloat16(w01);
    __nv_bfloat16 h10 = __float2bfloat16(w10), h11 = __float2bfloat16(w11);
    __nv_bfloat16 l00 = __float2bfloat16(w00 - __bfloat162float(h00));
    __nv_bfloat16 l01 = __float2bfloat16(w01 - __bfloat162float(h01));
    __nv_bfloat16 l10 = __float2bfloat16(w10 - __bfloat162float(h10));
    __nv_bfloat16 l11 = __float2bfloat16(w11 - __bfloat162float(h11));
    uint32_t* dst = g_B + i * 4;
    dst[0] = (uint32_t)*(unsigned short*)&h00 | ((uint32_t)*(unsigned short*)&h01 << 16);
    dst[1] = (uint32_t)*(unsigned short*)&h10 | ((uint32_t)*(unsigned short*)&h11 << 16);
    dst[2] = (uint32_t)*(unsigned short*)&l00 | ((uint32_t)*(unsigned short*)&l01 << 16);
    dst[3] = (uint32_t)*(unsigned short*)&l10 | ((uint32_t)*(unsigned short*)&l11 << 16);
}

__global__ void init_kernel(float* __restrict__ out) {
    int i = blockIdx.x * blockDim.x + threadIdx.x;
    if (i < NGRAPH * HID) out[i] = 0.f;
    if (i < NGRAPH) { g_m[i] = -INFINITY; g_sw[i] = 0.f; }
}

// ---------------------------------------------------------------------------
// score: persistent CTAs, HMMA bf16-split GEMM [128x128, K=256] per tile.
// B packed in smem (LDS.128/frag-quad), A via ldmatrix.x4. No atomics.
// dyn smem u32: B [0, 32768) ; A slabs: warp w at 32768 + w*1152 (hi [16][36],
// lo +576).
// ---------------------------------------------------------------------------
#define A_OFF 32768
#define A_WSZ 1152
#define A_PAD 36

__global__ void __launch_bounds__(256, 1) score_kernel(
    const float* __restrict__ x,
    const float* __restrict__ b1,
    const float* __restrict__ W2,
    const float* __restrict__ b2)
{
    extern __shared__ uint32_t sm[];
    __shared__ float sb1[128], sW2[128];

    const int tid = threadIdx.x, w = tid >> 5, l = tid & 31;
    const int gr = l >> 2, qc = l & 3;

    // B copy: 32768 u32 = 8192 float4
    {
        const float4* src = (const float4*)g_B;
        float4* dst = (float4*)sm;
        #pragma unroll
        for (int i = 0; i < 32; ++i) dst[tid + i * 256] = src[tid + i * 256];
    }
    if (tid < 128) { sb1[tid] = b1[tid]; sW2[tid] = W2[tid]; }
    __syncthreads();

    const float b2v = __ldg(&b2[0]);
    uint32_t* const Ahi = sm + A_OFF + w * A_WSZ;
    uint32_t* const Alo = Ahi + 576;
    // ldmatrix lane address (bytes): row (l&15), k-half (l>>4)
    const uint32_t a_hi_base = smem_u32(Ahi) + ((l & 15) * A_PAD + (l >> 4) * 4) * 4;
    const uint32_t a_lo_base = a_hi_base + 576 * 4;
    const uint4* const Bq = (const uint4*)sm;      // [kstep][nt][lane]
    const float4* xg = (const float4*)x;           // [node][64]

    for (int t = blockIdx.x; t < NTILES; t += NSM) {
        const int rbase = t * 128 + w * 16;

        float acc[16][4];
        #pragma unroll
        for (int nt = 0; nt < 16; ++nt)
            #pragma unroll
            for (int j = 0; j < 4; ++j) acc[nt][j] = 0.f;

        float4 v[8];
        #pragma unroll
        for (int i = 0; i < 8; ++i) {
            int f = i * 32 + l;
            v[i] = xg[(size_t)(rbase + (f >> 4)) * 64 + (f & 15)];
        }

        for (int c = 0; c < 4; ++c) {
            __syncwarp();
            #pragma unroll
            for (int i = 0; i < 8; ++i) {
                int f = i * 32 + l;
                int r = f >> 4, q = f & 15;
                __nv_bfloat162 h01 = __float22bfloat162_rn(make_float2(v[i].x, v[i].y));
                __nv_bfloat162 h23 = __float22bfloat162_rn(make_float2(v[i].z, v[i].w));
                float2 f01 = __bfloat1622float2(h01);
                float2 f23 = __bfloat1622float2(h23);
                __nv_bfloat162 l01 = __float22bfloat162_rn(make_float2(v[i].x - f01.x, v[i].y - f01.y));
                __nv_bfloat162 l23 = __float22bfloat162_rn(make_float2(v[i].z - f23.x, v[i].w - f23.y));
                Ahi[r * A_PAD + q * 2]     = *(uint32_t*)&h01;
                Ahi[r * A_PAD + q * 2 + 1] = *(uint32_t*)&h23;
                Alo[r * A_PAD + q * 2]     = *(uint32_t*)&l01;
                Alo[r * A_PAD + q * 2 + 1] = *(uint32_t*)&l23;
            }
            __syncwarp();
            if (c < 3) {
                #pragma unroll
                for (int i = 0; i < 8; ++i) {
                    int f = i * 32 + l;
                    v[i] = xg[(size_t)(rbase + (f >> 4)) * 64 + (c + 1) * 16 + (f & 15)];
                }
            }
            for (int k16 = 0; k16 < 4; ++k16) {
                uint32_t ah[4], al[4];
                ldsm_x4(ah, a_hi_base + k16 * 32);
                ldsm_x4(al, a_lo_base + k16 * 32);
                const uint4* Bk = Bq + ((c * 4 + k16) * 16) * 32 + l;
                #pragma unroll
                for (int nt = 0; nt < 16; ++nt) {
                    uint4 q = Bk[nt * 32];
                    mma_bf16(acc[nt], ah, q.x, q.y);
                    mma_bf16(acc[nt], ah, q.z, q.w);
                    mma_bf16(acc[nt], al, q.x, q.y);
                }
            }
        }

        float p0 = 0.f, p1 = 0.f;
        #pragma unroll
        for (int nt = 0; nt < 16; ++nt) {
            #pragma unroll
            for (int j = 0; j < 2; ++j) {
                int col = nt * 8 + qc * 2 + j;
                float bb = sb1[col], ww = sW2[col];
                float h0 = acc[nt][j] + bb;
                float e0 = __expf(2.f * h0);
                p0 = fmaf(1.f - __fdividef(2.f, e0 + 1.f), ww, p0);
                float h1 = acc[nt][2 + j] + bb;
                float e1 = __expf(2.f * h1);
                p1 = fmaf(1.f - __fdividef(2.f, e1 + 1.f), ww, p1);
            }
        }
        p0 += __shfl_xor_sync(0xFFFFFFFFu, p0, 1);
        p0 += __shfl_xor_sync(0xFFFFFFFFu, p0, 2);
        p1 += __shfl_xor_sync(0xFFFFFFFFu, p1, 1);
        p1 += __shfl_xor_sync(0xFFFFFFFFu, p1, 2);
        if (qc == 0) {
            g_s[rbase + gr]     = p0 + b2v;
            g_s[rbase + gr + 8] = p1 + b2v;
        }
    }
}

// ---------------- segment max over sorted batch (low-contention) -----------
__global__ void max_kernel(const int* __restrict__ batch) {
    int g = blockIdx.x * blockDim.x + threadIdx.x;   // 0..8191
    int start = g * 32;
    float m = -INFINITY;
    int curb = __ldg(&batch[start]);
    #pragma unroll 4
    for (int n = start; n < start + 32; ++n) {
        int b = __ldg(&batch[n]);
        if (b != curb) { atomicMaxF(&g_m[curb], m); m = -INFINITY; curb = b; }
        m = fmaxf(m, g_s[n]);
    }
    atomicMaxF(&g_m[curb], m);
}

// ---------------- softmax: w=exp(s-m), segment sums (low-contention) -------
__global__ void softmax_kernel(const int* __restrict__ batch) {
    int g = blockIdx.x * blockDim.x + threadIdx.x;
    int start = g * 32;
    float sum = 0.f;
    int curb = __ldg(&batch[start]);
    float m = __ldg(&g_m[curb]);
    #pragma unroll 4
    for (int n = start; n < start + 32; ++n) {
        int b = __ldg(&batch[n]);
        if (b != curb) {
            atomicAdd(&g_sw[curb], sum);
            sum = 0.f; curb = b; m = __ldg(&g_m[b]);
        }
        float wv = __expf(g_s[n] - m);
        g_s[n] = wv;
        sum += wv;
    }
    atomicAdd(&g_sw[curb], sum);
}

// ---------------- pool ----------------
__global__ void __launch_bounds__(256) pool_kernel(
    const float* __restrict__ x,
    const int* __restrict__ batch,
    float* __restrict__ out)
{
    const int tid = threadIdx.x;
    const int c4  = tid & 63;
    const int r   = tid >> 6;
    const int n0  = blockIdx.x * 128;
    const float4* x4 = (const float4*)x;

    float4 acc = make_float4(0.f, 0.f, 0.f, 0.f);
    int curb = batch[n0 + r];
    float inv = __fdividef(1.f, g_sw[curb] + 1e-8f);

    #pragma unroll 8
    for (int n = n0 + r; n < n0 + 128; n += 4) {
        int b = batch[n];
        if (b != curb) {
            float* o = &out[curb * HID + c4 * 4];
            atomicAdd(o + 0, acc.x); atomicAdd(o + 1, acc.y);
            atomicAdd(o + 2, acc.z); atomicAdd(o + 3, acc.w);
            acc = make_float4(0.f, 0.f, 0.f, 0.f);
            curb = b;
            inv = __fdividef(1.f, g_sw[b] + 1e-8f);
        }
        float wv = g_s[n] * inv;
        float4 vv = x4[(size_t)n * 64 + c4];
        acc.x = fmaf(vv.x, wv, acc.x); acc.y = fmaf(vv.y, wv, acc.y);
        acc.z = fmaf(vv.z, wv, acc.z); acc.w = fmaf(vv.w, wv, acc.w);
    }
    float* o = &out[curb * HID + c4 * 4];
    atomicAdd(o + 0, acc.x); atomicAdd(o + 1, acc.y);
    atomicAdd(o + 2, acc.z); atomicAdd(o + 3, acc.w);
}

extern "C" void kernel_launch(void* const* d_in, const int* in_sizes, int n_in,
                              void* d_out, int out_size) {
    const float* x     = (const float*)d_in[0];
    const int*   batch = (const int*)d_in[1];
    const float* W1    = (const float*)d_in[2];
    const float* b1    = (const float*)d_in[3];
    const float* W2    = (const float*)d_in[4];
    const float* b2    = (const float*)d_in[5];
    float* out = (float*)d_out;

    const int dyn = (A_OFF + 8 * A_WSZ) * 4;   // 131072 + 36864 = 167936 B
    cudaFuncSetAttribute(score_kernel, cudaFuncAttributeMaxDynamicSharedMemorySize, dyn);

    prep_kernel<<<32, 256>>>(W1);
    init_kernel<<<(NGRAPH * HID + 255) / 256, 256>>>(out);
    score_kernel<<<NSM, 256, dyn>>>(x, b1, W2, b2);
    max_kernel<<<32, 256>>>(batch);
    softmax_kernel<<<32, 256>>>(batch);
    pool_kernel<<<NUM_NODES / 128, 256>>>(x, batch, out);
}

// round 7
// speedup vs baseline: 1.0420x; 1.0420x over previous
#include <cuda_runtime.h>
#include <cuda_bf16.h>
#include <math.h>
#include <stdint.h>

#define NUM_NODES 262144
#define HID 256
#define NGRAPH 1024
#define NTILES (NUM_NODES / 128)   // 2048
#define NSM 148

// ---------------- scratch (static device globals) ----------------
__device__ float g_s[NUM_NODES];   // exp(score) = unnormalized weights
__device__ float g_sw[NGRAPH];     // segment sum of exp
// W1^T as b-fragment u32 pairs: [split][n=128][132 u32(pad)] ; kp = k/2
#define BROW 132
#define BSPLIT (128 * BROW)        // 16896 u32
__device__ uint32_t g_B[2 * BSPLIT];

__device__ __forceinline__ void mma_bf16(float* c, const uint32_t* a,
                                         uint32_t b0, uint32_t b1) {
    asm volatile(
        "mma.sync.aligned.m16n8k16.row.col.f32.bf16.bf16.f32 "
        "{%0,%1,%2,%3}, {%4,%5,%6,%7}, {%8,%9}, {%0,%1,%2,%3};"
        : "+f"(c[0]), "+f"(c[1]), "+f"(c[2]), "+f"(c[3])
        : "r"(a[0]), "r"(a[1]), "r"(a[2]), "r"(a[3]), "r"(b0), "r"(b1));
}

// ---------------- prep: W1^T -> split bf16 u32 pairs ----------------
__global__ void prep_kernel(const float* __restrict__ W1) {  // W1[256][128]
    int i = blockIdx.x * 256 + threadIdx.x;   // 0..16383
    if (i >= 16384) return;
    int n = i >> 7, kp = i & 127;
    float w0 = W1[(2 * kp) * 128 + n];
    float w1 = W1[(2 * kp + 1) * 128 + n];
    __nv_bfloat16 h0 = __float2bfloat16(w0), h1 = __float2bfloat16(w1);
    __nv_bfloat16 l0 = __float2bfloat16(w0 - __bfloat162float(h0));
    __nv_bfloat16 l1 = __float2bfloat16(w1 - __bfloat162float(h1));
    uint32_t hv = (uint32_t)*(unsigned short*)&h0 | ((uint32_t)*(unsigned short*)&h1 << 16);
    uint32_t lv = (uint32_t)*(unsigned short*)&l0 | ((uint32_t)*(unsigned short*)&l1 << 16);
    g_B[0 * BSPLIT + n * BROW + kp] = hv;
    g_B[1 * BSPLIT + n * BROW + kp] = lv;
}

__global__ void init_kernel(float* __restrict__ out) {
    int i = blockIdx.x * blockDim.x + threadIdx.x;
    if (i < NGRAPH * HID) out[i] = 0.f;
    if (i < NGRAPH) g_sw[i] = 0.f;
}

// ---------------------------------------------------------------------------
// score: persistent CTAs, HMMA bf16-split GEMM [128 x 128, K=256] per tile
// (R5 core, known-good). Epilogue fuses tanh*W2 AND exp -> g_s = exp(s).
// dyn smem u32: B [0, 33792) ; A slabs: warp w at 33792 + w*1152 (hi [16][36],
// lo +576).
// ---------------------------------------------------------------------------
#define A_OFF 33792
#define A_WSZ 1152
#define A_PAD 36

__global__ void __launch_bounds__(256, 1) score_kernel(
    const float* __restrict__ x,
    const float* __restrict__ b1,
    const float* __restrict__ W2,
    const float* __restrict__ b2)
{
    extern __shared__ uint32_t sm[];
    __shared__ float sb1[128], sW2[128];

    const int tid = threadIdx.x, w = tid >> 5, l = tid & 31;
    const int gr = l >> 2, qc = l & 3;            // frag row / col-quad

    {   // B copy: 33792 u32 = 8448 float4
        const float4* src = (const float4*)g_B;
        float4* dst = (float4*)sm;
        for (int i = tid; i < 8448; i += 256) dst[i] = src[i];
    }
    if (tid < 128) { sb1[tid] = b1[tid]; sW2[tid] = W2[tid]; }
    __syncthreads();

    const float b2v = __ldg(&b2[0]);
    uint32_t* const Ahi = sm + A_OFF + w * A_WSZ;
    uint32_t* const Alo = Ahi + 576;
    const float4* xg = (const float4*)x;          // [node][64]

    for (int t = blockIdx.x; t < NTILES; t += NSM) {
        const int rbase = t * 128 + w * 16;

        float acc[16][4];
        #pragma unroll
        for (int nt = 0; nt < 16; ++nt)
            #pragma unroll
            for (int j = 0; j < 4; ++j) acc[nt][j] = 0.f;

        float4 v[8];
        #pragma unroll
        for (int i = 0; i < 8; ++i) {
            int f = i * 32 + l;
            v[i] = xg[(size_t)(rbase + (f >> 4)) * 64 + (f & 15)];
        }

        for (int c = 0; c < 4; ++c) {
            __syncwarp();
            #pragma unroll
            for (int i = 0; i < 8; ++i) {
                int f = i * 32 + l;
                int r = f >> 4, q = f & 15;
                __nv_bfloat162 h01 = __float22bfloat162_rn(make_float2(v[i].x, v[i].y));
                __nv_bfloat162 h23 = __float22bfloat162_rn(make_float2(v[i].z, v[i].w));
                float2 f01 = __bfloat1622float2(h01);
                float2 f23 = __bfloat1622float2(h23);
                __nv_bfloat162 l01 = __float22bfloat162_rn(make_float2(v[i].x - f01.x, v[i].y - f01.y));
                __nv_bfloat162 l23 = __float22bfloat162_rn(make_float2(v[i].z - f23.x, v[i].w - f23.y));
                Ahi[r * A_PAD + q * 2]     = *(uint32_t*)&h01;
                Ahi[r * A_PAD + q * 2 + 1] = *(uint32_t*)&h23;
                Alo[r * A_PAD + q * 2]     = *(uint32_t*)&l01;
                Alo[r * A_PAD + q * 2 + 1] = *(uint32_t*)&l23;
            }
            __syncwarp();
            if (c < 3) {
                #pragma unroll
                for (int i = 0; i < 8; ++i) {
                    int f = i * 32 + l;
                    v[i] = xg[(size_t)(rbase + (f >> 4)) * 64 + (c + 1) * 16 + (f & 15)];
                }
            }
            for (int k16 = 0; k16 < 4; ++k16) {
                uint32_t ah[4], al[4];
                int ab = k16 * 8 + qc;
                ah[0] = Ahi[gr * A_PAD + ab];       ah[1] = Ahi[(gr + 8) * A_PAD + ab];
                ah[2] = Ahi[gr * A_PAD + ab + 4];   ah[3] = Ahi[(gr + 8) * A_PAD + ab + 4];
                al[0] = Alo[gr * A_PAD + ab];       al[1] = Alo[(gr + 8) * A_PAD + ab];
                al[2] = Alo[gr * A_PAD + ab + 4];   al[3] = Alo[(gr + 8) * A_PAD + ab + 4];
                const int kp = c * 32 + k16 * 8 + qc;
                #pragma unroll
                for (int nt = 0; nt < 16; ++nt) {
                    const uint32_t* Bh = sm + (nt * 8 + gr) * BROW + kp;
                    const uint32_t* Bl = Bh + BSPLIT;
                    uint32_t bh0 = Bh[0], bh1 = Bh[4];
                    uint32_t bl0 = Bl[0], bl1 = Bl[4];
                    mma_bf16(acc[nt], ah, bh0, bh1);
                    mma_bf16(acc[nt], ah, bl0, bl1);
                    mma_bf16(acc[nt], al, bh0, bh1);
                }
            }
        }

        float p0 = 0.f, p1 = 0.f;
        #pragma unroll
        for (int nt = 0; nt < 16; ++nt) {
            #pragma unroll
            for (int j = 0; j < 2; ++j) {
                int col = nt * 8 + qc * 2 + j;
                float bb = sb1[col], ww = sW2[col];
                float h0 = acc[nt][j] + bb;
                float e0 = __expf(2.f * h0);
                p0 = fmaf(1.f - __fdividef(2.f, e0 + 1.f), ww, p0);
                float h1 = acc[nt][2 + j] + bb;
                float e1 = __expf(2.f * h1);
                p1 = fmaf(1.f - __fdividef(2.f, e1 + 1.f), ww, p1);
            }
        }
        p0 += __shfl_xor_sync(0xFFFFFFFFu, p0, 1);
        p0 += __shfl_xor_sync(0xFFFFFFFFu, p0, 2);
        p1 += __shfl_xor_sync(0xFFFFFFFFu, p1, 1);
        p1 += __shfl_xor_sync(0xFFFFFFFFu, p1, 2);
        if (qc == 0) {
            // g_s stores exp(score); max-subtraction cancels (see analysis)
            g_s[rbase + gr]     = __expf(p0 + b2v);
            g_s[rbase + gr + 8] = __expf(p1 + b2v);
        }
    }
}

// ---------------- segment sum of exp (coalesced, low-contention) -----------
// 256 blocks x 256 thr; thread g owns nodes 4g..4g+3 (float4/int4 loads).
__global__ void __launch_bounds__(256) sum_kernel(const int* __restrict__ batch) {
    int g = blockIdx.x * blockDim.x + threadIdx.x;   // 0..65535
    int4  b4 = ((const int4*)batch)[g];
    float4 w4 = ((const float4*)g_s)[g];
    float sum = w4.x;
    int curb = b4.x;
    if (b4.y != curb) { atomicAdd(&g_sw[curb], sum); sum = 0.f; curb = b4.y; }
    sum += w4.y;
    if (b4.z != curb) { atomicAdd(&g_sw[curb], sum); sum = 0.f; curb = b4.z; }
    sum += w4.z;
    if (b4.w != curb) { atomicAdd(&g_sw[curb], sum); sum = 0.f; curb = b4.w; }
    sum += w4.w;
    atomicAdd(&g_sw[curb], sum);
}

// ---------------- pool ----------------
__global__ void __launch_bounds__(256) pool_kernel(
    const float* __restrict__ x,
    const int* __restrict__ batch,
    float* __restrict__ out)
{
    const int tid = threadIdx.x;
    const int c4  = tid & 63;
    const int r   = tid >> 6;
    const int n0  = blockIdx.x * 128;
    const float4* x4 = (const float4*)x;

    float4 acc = make_float4(0.f, 0.f, 0.f, 0.f);
    int curb = batch[n0 + r];
    float inv = __fdividef(1.f, g_sw[curb] + 1e-8f);

    #pragma unroll 8
    for (int n = n0 + r; n < n0 + 128; n += 4) {
        int b = batch[n];
        if (b != curb) {
            float* o = &out[curb * HID + c4 * 4];
            atomicAdd(o + 0, acc.x); atomicAdd(o + 1, acc.y);
            atomicAdd(o + 2, acc.z); atomicAdd(o + 3, acc.w);
            acc = make_float4(0.f, 0.f, 0.f, 0.f);
            curb = b;
            inv = __fdividef(1.f, g_sw[b] + 1e-8f);
        }
        float wv = g_s[n] * inv;
        float4 vv = x4[(size_t)n * 64 + c4];
        acc.x = fmaf(vv.x, wv, acc.x); acc.y = fmaf(vv.y, wv, acc.y);
        acc.z = fmaf(vv.z, wv, acc.z); acc.w = fmaf(vv.w, wv, acc.w);
    }
    float* o = &out[curb * HID + c4 * 4];
    atomicAdd(o + 0, acc.x); atomicAdd(o + 1, acc.y);
    atomicAdd(o + 2, acc.z); atomicAdd(o + 3, acc.w);
}

extern "C" void kernel_launch(void* const* d_in, const int* in_sizes, int n_in,
                              void* d_out, int out_size) {
    const float* x     = (const float*)d_in[0];
    const int*   batch = (const int*)d_in[1];
    const float* W1    = (const float*)d_in[2];
    const float* b1    = (const float*)d_in[3];
    const float* W2    = (const float*)d_in[4];
    const float* b2    = (const float*)d_in[5];
    float* out = (float*)d_out;

    const int dyn = (A_OFF + 8 * A_WSZ) * 4;   // 135168 + 36864 = 172032 B
    cudaFuncSetAttribute(score_kernel, cudaFuncAttributeMaxDynamicSharedMemorySize, dyn);

    prep_kernel<<<64, 256>>>(W1);
    init_kernel<<<(NGRAPH * HID + 255) / 256, 256>>>(out);
    score_kernel<<<NSM, 256, dyn>>>(x, b1, W2, b2);
    sum_kernel<<<256, 256>>>(batch);
    pool_kernel<<<NUM_NODES / 128, 256>>>(x, batch, out);
}

// round 8
// speedup vs baseline: 1.4927x; 1.4326x over previous
#include <cuda_runtime.h>
#include <cuda_bf16.h>
#include <math.h>
#include <stdint.h>

#define NUM_NODES 262144
#define HID 256
#define NGRAPH 1024
#define NTILES (NUM_NODES / 128)   // 2048
#define NSM 148

// ---------------- scratch (static device globals) ----------------
__device__ float g_s[NUM_NODES];   // exp(score) = unnormalized weights
__device__ float g_sw[NGRAPH];     // segment sum of exp
// W1^T packed b-frag quads: [kstep 0..15][nt 0..15][lane 0..31][bh0,bh1,bl0,bl1]
__device__ uint32_t g_B[16 * 16 * 32 * 4];   // 32768 u32 = 128KB

__device__ __forceinline__ void mma_bf16(float* c, const uint32_t* a,
                                         uint32_t b0, uint32_t b1) {
    asm volatile(
        "mma.sync.aligned.m16n8k16.row.col.f32.bf16.bf16.f32 "
        "{%0,%1,%2,%3}, {%4,%5,%6,%7}, {%8,%9}, {%0,%1,%2,%3};"
        : "+f"(c[0]), "+f"(c[1]), "+f"(c[2]), "+f"(c[3])
        : "r"(a[0]), "r"(a[1]), "r"(a[2]), "r"(a[3]), "r"(b0), "r"(b1));
}

// ---------------- prep: W1^T -> packed split-bf16 b-frag quads -------------
// quad for (ks, nt, lane l): n = nt*8 + (l>>2), kp0 = (ks>>2)*32 + (ks&3)*8
// + (l&3), kp1 = kp0+4  ==  exactly the R5 per-u32 read pattern.
__global__ void prep_kernel(const float* __restrict__ W1) {  // W1[256][128]
    int i = blockIdx.x * 256 + threadIdx.x;   // 0..8191
    if (i >= 8192) return;
    int l = i & 31, nt = (i >> 5) & 15, ks = i >> 9;
    int gr = l >> 2, qc = l & 3;
    int n = nt * 8 + gr;
    int kp0 = (ks >> 2) * 32 + (ks & 3) * 8 + qc;
    int kp1 = kp0 + 4;
    float w00 = W1[(2 * kp0) * 128 + n],     w01 = W1[(2 * kp0 + 1) * 128 + n];
    float w10 = W1[(2 * kp1) * 128 + n],     w11 = W1[(2 * kp1 + 1) * 128 + n];
    __nv_bfloat16 h00 = __float2bfloat16(w00), h01 = __float2bfloat16(w01);
    __nv_bfloat16 h10 = __float2bfloat16(w10), h11 = __float2bfloat16(w11);
    __nv_bfloat16 l00 = __float2bfloat16(w00 - __bfloat162float(h00));
    __nv_bfloat16 l01 = __float2bfloat16(w01 - __bfloat162float(h01));
    __nv_bfloat16 l10 = __float2bfloat16(w10 - __bfloat162float(h10));
    __nv_bfloat16 l11 = __float2bfloat16(w11 - __bfloat162float(h11));
    uint32_t* dst = g_B + i * 4;
    dst[0] = (uint32_t)*(unsigned short*)&h00 | ((uint32_t)*(unsigned short*)&h01 << 16);
    dst[1] = (uint32_t)*(unsigned short*)&h10 | ((uint32_t)*(unsigned short*)&h11 << 16);
    dst[2] = (uint32_t)*(unsigned short*)&l00 | ((uint32_t)*(unsigned short*)&l01 << 16);
    dst[3] = (uint32_t)*(unsigned short*)&l10 | ((uint32_t)*(unsigned short*)&l11 << 16);
}

__global__ void init_kernel(float* __restrict__ out) {
    int i = blockIdx.x * blockDim.x + threadIdx.x;
    if (i < NGRAPH * HID) out[i] = 0.f;
    if (i < NGRAPH) g_sw[i] = 0.f;
}

// ---------------------------------------------------------------------------
// score: persistent CTAs, HMMA bf16-split GEMM [128x128, K=256] per tile.
// A path = R5 (direct LDS.32 from padded slab). B path = packed quads
// (1 LDS.128 per nt per k16). Epilogue fuses tanh*W2 and exp.
// dyn smem u32: B quads [0, 32768) ; A slabs: warp w at 32768 + w*1152
// (hi [16][36], lo +576).
// ---------------------------------------------------------------------------
#define A_OFF 32768
#define A_WSZ 1152
#define A_PAD 36

__global__ void __launch_bounds__(256, 1) score_kernel(
    const float* __restrict__ x,
    const float* __restrict__ b1,
    const float* __restrict__ W2,
    const float* __restrict__ b2)
{
    extern __shared__ uint32_t sm[];
    __shared__ float sb1[128], sW2[128];

    const int tid = threadIdx.x, w = tid >> 5, l = tid & 31;
    const int gr = l >> 2, qc = l & 3;

    {   // B copy: 32768 u32 = 8192 float4
        const float4* src = (const float4*)g_B;
        float4* dst = (float4*)sm;
        #pragma unroll
        for (int i = 0; i < 32; ++i) dst[tid + i * 256] = src[tid + i * 256];
    }
    if (tid < 128) { sb1[tid] = b1[tid]; sW2[tid] = W2[tid]; }
    __syncthreads();

    const float b2v = __ldg(&b2[0]);
    uint32_t* const Ahi = sm + A_OFF + w * A_WSZ;
    uint32_t* const Alo = Ahi + 576;
    const uint4* const Bq = (const uint4*)sm;     // [kstep][nt][lane]
    const float4* xg = (const float4*)x;          // [node][64]

    for (int t = blockIdx.x; t < NTILES; t += NSM) {
        const int rbase = t * 128 + w * 16;

        float acc[16][4];
        #pragma unroll
        for (int nt = 0; nt < 16; ++nt)
            #pragma unroll
            for (int j = 0; j < 4; ++j) acc[nt][j] = 0.f;

        float4 v[8];
        #pragma unroll
        for (int i = 0; i < 8; ++i) {
            int f = i * 32 + l;
            v[i] = xg[(size_t)(rbase + (f >> 4)) * 64 + (f & 15)];
        }

        for (int c = 0; c < 4; ++c) {
            __syncwarp();
            #pragma unroll
            for (int i = 0; i < 8; ++i) {
                int f = i * 32 + l;
                int r = f >> 4, q = f & 15;
                __nv_bfloat162 h01 = __float22bfloat162_rn(make_float2(v[i].x, v[i].y));
                __nv_bfloat162 h23 = __float22bfloat162_rn(make_float2(v[i].z, v[i].w));
                float2 f01 = __bfloat1622float2(h01);
                float2 f23 = __bfloat1622float2(h23);
                __nv_bfloat162 l01 = __float22bfloat162_rn(make_float2(v[i].x - f01.x, v[i].y - f01.y));
                __nv_bfloat162 l23 = __float22bfloat162_rn(make_float2(v[i].z - f23.x, v[i].w - f23.y));
                Ahi[r * A_PAD + q * 2]     = *(uint32_t*)&h01;
                Ahi[r * A_PAD + q * 2 + 1] = *(uint32_t*)&h23;
                Alo[r * A_PAD + q * 2]     = *(uint32_t*)&l01;
                Alo[r * A_PAD + q * 2 + 1] = *(uint32_t*)&l23;
            }
            __syncwarp();
            if (c < 3) {
                #pragma unroll
                for (int i = 0; i < 8; ++i) {
                    int f = i * 32 + l;
                    v[i] = xg[(size_t)(rbase + (f >> 4)) * 64 + (c + 1) * 16 + (f & 15)];
                }
            }
            for (int k16 = 0; k16 < 4; ++k16) {
                uint32_t ah[4], al[4];
                int ab = k16 * 8 + qc;
                ah[0] = Ahi[gr * A_PAD + ab];       ah[1] = Ahi[(gr + 8) * A_PAD + ab];
                ah[2] = Ahi[gr * A_PAD + ab + 4];   ah[3] = Ahi[(gr + 8) * A_PAD + ab + 4];
                al[0] = Alo[gr * A_PAD + ab];       al[1] = Alo[(gr + 8) * A_PAD + ab];
                al[2] = Alo[gr * A_PAD + ab + 4];   al[3] = Alo[(gr + 8) * A_PAD + ab + 4];
                const uint4* Bk = Bq + ((c * 4 + k16) * 16) * 32 + l;
                #pragma unroll
                for (int nt = 0; nt < 16; ++nt) {
                    uint4 q = Bk[nt * 32];          // LDS.128, conflict-free
                    mma_bf16(acc[nt], ah, q.x, q.y);
                    mma_bf16(acc[nt], ah, q.z, q.w);
                    mma_bf16(acc[nt], al, q.x, q.y);
                }
            }
        }

        float p0 = 0.f, p1 = 0.f;
        #pragma unroll
        for (int nt = 0; nt < 16; ++nt) {
            #pragma unroll
            for (int j = 0; j < 2; ++j) {
                int col = nt * 8 + qc * 2 + j;
                float bb = sb1[col], ww = sW2[col];
                float h0 = acc[nt][j] + bb;
                float e0 = __expf(2.f * h0);
                p0 = fmaf(1.f - __fdividef(2.f, e0 + 1.f), ww, p0);
                float h1 = acc[nt][2 + j] + bb;
                float e1 = __expf(2.f * h1);
                p1 = fmaf(1.f - __fdividef(2.f, e1 + 1.f), ww, p1);
            }
        }
        p0 += __shfl_xor_sync(0xFFFFFFFFu, p0, 1);
        p0 += __shfl_xor_sync(0xFFFFFFFFu, p0, 2);
        p1 += __shfl_xor_sync(0xFFFFFFFFu, p1, 1);
        p1 += __shfl_xor_sync(0xFFFFFFFFu, p1, 2);
        if (qc == 0) {
            // g_s stores exp(score); max-subtraction cancels exactly
            g_s[rbase + gr]     = __expf(p0 + b2v);
            g_s[rbase + gr + 8] = __expf(p1 + b2v);
        }
    }
}

// ---------------- segment sum of exp (coalesced, low-contention) -----------
__global__ void __launch_bounds__(256) sum_kernel(const int* __restrict__ batch) {
    int g = blockIdx.x * blockDim.x + threadIdx.x;   // 0..65535
    int4  b4 = ((const int4*)batch)[g];
    float4 w4 = ((const float4*)g_s)[g];
    float sum = w4.x;
    int curb = b4.x;
    if (b4.y != curb) { atomicAdd(&g_sw[curb], sum); sum = 0.f; curb = b4.y; }
    sum += w4.y;
    if (b4.z != curb) { atomicAdd(&g_sw[curb], sum); sum = 0.f; curb = b4.z; }
    sum += w4.z;
    if (b4.w != curb) { atomicAdd(&g_sw[curb], sum); sum = 0.f; curb = b4.w; }
    sum += w4.w;
    atomicAdd(&g_sw[curb], sum);
}

// ---------------- pool ----------------
__global__ void __launch_bounds__(256) pool_kernel(
    const float* __restrict__ x,
    const int* __restrict__ batch,
    float* __restrict__ out)
{
    const int tid = threadIdx.x;
    const int c4  = tid & 63;
    const int r   = tid >> 6;
    const int n0  = blockIdx.x * 128;
    const float4* x4 = (const float4*)x;

    float4 acc = make_float4(0.f, 0.f, 0.f, 0.f);
    int curb = batch[n0 + r];
    float inv = __fdividef(1.f, g_sw[curb] + 1e-8f);

    #pragma unroll 8
    for (int n = n0 + r; n < n0 + 128; n += 4) {
        int b = batch[n];
        if (b != curb) {
            float* o = &out[curb * HID + c4 * 4];
            atomicAdd(o + 0, acc.x); atomicAdd(o + 1, acc.y);
            atomicAdd(o + 2, acc.z); atomicAdd(o + 3, acc.w);
            acc = make_float4(0.f, 0.f, 0.f, 0.f);
            curb = b;
            inv = __fdividef(1.f, g_sw[b] + 1e-8f);
        }
        float wv = g_s[n] * inv;
        float4 vv = x4[(size_t)n * 64 + c4];
        acc.x = fmaf(vv.x, wv, acc.x); acc.y = fmaf(vv.y, wv, acc.y);
        acc.z = fmaf(vv.z, wv, acc.z); acc.w = fmaf(vv.w, wv, acc.w);
    }
    float* o = &out[curb * HID + c4 * 4];
    atomicAdd(o + 0, acc.x); atomicAdd(o + 1, acc.y);
    atomicAdd(o + 2, acc.z); atomicAdd(o + 3, acc.w);
}

extern "C" void kernel_launch(void* const* d_in, const int* in_sizes, int n_in,
                              void* d_out, int out_size) {
    const float* x     = (const float*)d_in[0];
    const int*   batch = (const int*)d_in[1];
    const float* W1    = (const float*)d_in[2];
    const float* b1    = (const float*)d_in[3];
    const float* W2    = (const float*)d_in[4];
    const float* b2    = (const float*)d_in[5];
    float* out = (float*)d_out;

    const int dyn = (A_OFF + 8 * A_WSZ) * 4;   // 131072 + 36864 = 167936 B
    cudaFuncSetAttribute(score_kernel, cudaFuncAttributeMaxDynamicSharedMemorySize, dyn);

    prep_kernel<<<32, 256>>>(W1);
    init_kernel<<<(NGRAPH * HID + 255) / 256, 256>>>(out);
    score_kernel<<<NSM, 256, dyn>>>(x, b1, W2, b2);
    sum_kernel<<<256, 256>>>(batch);
    pool_kernel<<<NUM_NODES / 128, 256>>>(x, batch, out);
}

// round 9
// speedup vs baseline: 1.8938x; 1.2687x over previous
#include <cuda_runtime.h>
#include <cuda_bf16.h>
#include <math.h>
#include <stdint.h>

#define NUM_NODES 262144
#define HID 256
#define NGRAPH 1024
#define NTILES (NUM_NODES / 128)   // 2048
#define NSM 148

// ---------------- scratch (static device globals) ----------------
__device__ float g_sw[NGRAPH];     // segment sum of exp(score)
// W1^T packed b-frag quads: [kstep 0..15][nt 0..15][lane 0..31][bh0,bh1,bl0,bl1]
__device__ uint32_t g_B[16 * 16 * 32 * 4];   // 32768 u32 = 128KB

__device__ __forceinline__ void mma_bf16(float* c, const uint32_t* a,
                                         uint32_t b0, uint32_t b1) {
    asm volatile(
        "mma.sync.aligned.m16n8k16.row.col.f32.bf16.bf16.f32 "
        "{%0,%1,%2,%3}, {%4,%5,%6,%7}, {%8,%9}, {%0,%1,%2,%3};"
        : "+f"(c[0]), "+f"(c[1]), "+f"(c[2]), "+f"(c[3])
        : "r"(a[0]), "r"(a[1]), "r"(a[2]), "r"(a[3]), "r"(b0), "r"(b1));
}

// ---------------- prep: W1^T -> packed split-bf16 b-frag quads -------------
__global__ void prep_kernel(const float* __restrict__ W1) {  // W1[256][128]
    int i = blockIdx.x * 256 + threadIdx.x;   // 0..8191
    if (i >= 8192) return;
    int l = i & 31, nt = (i >> 5) & 15, ks = i >> 9;
    int gr = l >> 2, qc = l & 3;
    int n = nt * 8 + gr;
    int kp0 = (ks >> 2) * 32 + (ks & 3) * 8 + qc;
    int kp1 = kp0 + 4;
    float w00 = W1[(2 * kp0) * 128 + n],     w01 = W1[(2 * kp0 + 1) * 128 + n];
    float w10 = W1[(2 * kp1) * 128 + n],     w11 = W1[(2 * kp1 + 1) * 128 + n];
    __nv_bfloat16 h00 = __float2bfloat16(w00), h01 = __float2bfloat16(w01);
    __nv_bfloat16 h10 = __float2bfloat16(w10), h11 = __float2bfloat16(w11);
    __nv_bfloat16 l00 = __float2bfloat16(w00 - __bfloat162float(h00));
    __nv_bfloat16 l01 = __float2bfloat16(w01 - __bfloat162float(h01));
    __nv_bfloat16 l10 = __float2bfloat16(w10 - __bfloat162float(h10));
    __nv_bfloat16 l11 = __float2bfloat16(w11 - __bfloat162float(h11));
    uint32_t* dst = g_B + i * 4;
    dst[0] = (uint32_t)*(unsigned short*)&h00 | ((uint32_t)*(unsigned short*)&h01 << 16);
    dst[1] = (uint32_t)*(unsigned short*)&h10 | ((uint32_t)*(unsigned short*)&h11 << 16);
    dst[2] = (uint32_t)*(unsigned short*)&l00 | ((uint32_t)*(unsigned short*)&l01 << 16);
    dst[3] = (uint32_t)*(unsigned short*)&l10 | ((uint32_t)*(unsigned short*)&l11 << 16);
}

__global__ void init_kernel(float* __restrict__ out) {
    int i = blockIdx.x * blockDim.x + threadIdx.x;
    if (i < NGRAPH * HID) out[i] = 0.f;
    if (i < NGRAPH) g_sw[i] = 0.f;
}

// ---------------------------------------------------------------------------
// fused score+pool: persistent CTAs. Per 128-node tile: HMMA bf16-split GEMM
// (R8 core) -> scores; epilogue computes w = exp(s), then each warp re-reads
// its 16x256 x rows (L2-hot) and accumulates out[b] += x*w and g_sw[b] += w,
// flushing atomics only at segment boundaries. Normalize divides later.
// dyn smem u32: B quads [0, 32768) ; A slabs: warp w at 32768 + w*1152.
// ---------------------------------------------------------------------------
#define A_OFF 32768
#define A_WSZ 1152
#define A_PAD 36

__global__ void __launch_bounds__(256, 1) score_kernel(
    const float* __restrict__ x,
    const int* __restrict__ batch,
    const float* __restrict__ b1,
    const float* __restrict__ W2,
    const float* __restrict__ b2,
    float* __restrict__ out)
{
    extern __shared__ uint32_t sm[];
    __shared__ float sb1[128], sW2[128];

    const int tid = threadIdx.x, w = tid >> 5, l = tid & 31;
    const int gr = l >> 2, qc = l & 3;

    {   // B copy: 32768 u32 = 8192 float4
        const float4* src = (const float4*)g_B;
        float4* dst = (float4*)sm;
        #pragma unroll
        for (int i = 0; i < 32; ++i) dst[tid + i * 256] = src[tid + i * 256];
    }
    if (tid < 128) { sb1[tid] = b1[tid]; sW2[tid] = W2[tid]; }
    __syncthreads();

    const float b2v = __ldg(&b2[0]);
    uint32_t* const Ahi = sm + A_OFF + w * A_WSZ;
    uint32_t* const Alo = Ahi + 576;
    const uint4* const Bq = (const uint4*)sm;     // [kstep][nt][lane]
    const float4* xg = (const float4*)x;          // [node][64]

    for (int t = blockIdx.x; t < NTILES; t += NSM) {
        const int rbase = t * 128 + w * 16;

        float acc[16][4];
        #pragma unroll
        for (int nt = 0; nt < 16; ++nt)
            #pragma unroll
            for (int j = 0; j < 4; ++j) acc[nt][j] = 0.f;

        float4 v[8];
        #pragma unroll
        for (int i = 0; i < 8; ++i) {
            int f = i * 32 + l;
            v[i] = xg[(size_t)(rbase + (f >> 4)) * 64 + (f & 15)];
        }

        for (int c = 0; c < 4; ++c) {
            __syncwarp();
            #pragma unroll
            for (int i = 0; i < 8; ++i) {
                int f = i * 32 + l;
                int r = f >> 4, q = f & 15;
                __nv_bfloat162 h01 = __float22bfloat162_rn(make_float2(v[i].x, v[i].y));
                __nv_bfloat162 h23 = __float22bfloat162_rn(make_float2(v[i].z, v[i].w));
                float2 f01 = __bfloat1622float2(h01);
                float2 f23 = __bfloat1622float2(h23);
                __nv_bfloat162 l01 = __float22bfloat162_rn(make_float2(v[i].x - f01.x, v[i].y - f01.y));
                __nv_bfloat162 l23 = __float22bfloat162_rn(make_float2(v[i].z - f23.x, v[i].w - f23.y));
                Ahi[r * A_PAD + q * 2]     = *(uint32_t*)&h01;
                Ahi[r * A_PAD + q * 2 + 1] = *(uint32_t*)&h23;
                Alo[r * A_PAD + q * 2]     = *(uint32_t*)&l01;
                Alo[r * A_PAD + q * 2 + 1] = *(uint32_t*)&l23;
            }
            __syncwarp();
            if (c < 3) {
                #pragma unroll
                for (int i = 0; i < 8; ++i) {
                    int f = i * 32 + l;
                    v[i] = xg[(size_t)(rbase + (f >> 4)) * 64 + (c + 1) * 16 + (f & 15)];
                }
            }
            for (int k16 = 0; k16 < 4; ++k16) {
                uint32_t ah[4], al[4];
                int ab = k16 * 8 + qc;
                ah[0] = Ahi[gr * A_PAD + ab];       ah[1] = Ahi[(gr + 8) * A_PAD + ab];
                ah[2] = Ahi[gr * A_PAD + ab + 4];   ah[3] = Ahi[(gr + 8) * A_PAD + ab + 4];
                al[0] = Alo[gr * A_PAD + ab];       al[1] = Alo[(gr + 8) * A_PAD + ab];
                al[2] = Alo[gr * A_PAD + ab + 4];   al[3] = Alo[(gr + 8) * A_PAD + ab + 4];
                const uint4* Bk = Bq + ((c * 4 + k16) * 16) * 32 + l;
                #pragma unroll
                for (int nt = 0; nt < 16; ++nt) {
                    uint4 q = Bk[nt * 32];          // LDS.128, conflict-free
                    mma_bf16(acc[nt], ah, q.x, q.y);
                    mma_bf16(acc[nt], ah, q.z, q.w);
                    mma_bf16(acc[nt], al, q.x, q.y);
                }
            }
        }

        // epilogue: row scores. After quad xor-reduce, all 4 lanes of quad gr
        // hold p0 (row gr) and p1 (row gr+8).
        float p0 = 0.f, p1 = 0.f;
        #pragma unroll
        for (int nt = 0; nt < 16; ++nt) {
            #pragma unroll
            for (int j = 0; j < 2; ++j) {
                int col = nt * 8 + qc * 2 + j;
                float bb = sb1[col], ww = sW2[col];
                float h0 = acc[nt][j] + bb;
                float e0 = __expf(2.f * h0);
                p0 = fmaf(1.f - __fdividef(2.f, e0 + 1.f), ww, p0);
                float h1 = acc[nt][2 + j] + bb;
                float e1 = __expf(2.f * h1);
                p1 = fmaf(1.f - __fdividef(2.f, e1 + 1.f), ww, p1);
            }
        }
        p0 += __shfl_xor_sync(0xFFFFFFFFu, p0, 1);
        p0 += __shfl_xor_sync(0xFFFFFFFFu, p0, 2);
        p1 += __shfl_xor_sync(0xFFFFFFFFu, p1, 1);
        p1 += __shfl_xor_sync(0xFFFFFFFFu, p1, 2);

        // ---- fused pool phase: re-read 16 rows x 256 cols (L2-hot) ----
        float4 accA = make_float4(0.f, 0.f, 0.f, 0.f);
        float4 accB = make_float4(0.f, 0.f, 0.f, 0.f);
        float wsum = 0.f;
        int curb = __ldg(&batch[rbase]);
        #pragma unroll
        for (int r = 0; r < 16; ++r) {
            float sc = (r < 8) ? __shfl_sync(0xFFFFFFFFu, p0, r * 4)
                               : __shfl_sync(0xFFFFFFFFu, p1, (r - 8) * 4);
            float wv = __expf(sc + b2v);
            int b = __ldg(&batch[rbase + r]);
            if (b != curb) {
                float* o = &out[curb * HID + l * 4];
                atomicAdd(o + 0, accA.x); atomicAdd(o + 1, accA.y);
                atomicAdd(o + 2, accA.z); atomicAdd(o + 3, accA.w);
                float* o2 = o + 128;
                atomicAdd(o2 + 0, accB.x); atomicAdd(o2 + 1, accB.y);
                atomicAdd(o2 + 2, accB.z); atomicAdd(o2 + 3, accB.w);
                if (l == 0) atomicAdd(&g_sw[curb], wsum);
                accA = make_float4(0.f, 0.f, 0.f, 0.f);
                accB = make_float4(0.f, 0.f, 0.f, 0.f);
                wsum = 0.f;
                curb = b;
            }
            wsum += wv;
            float4 xa = xg[(size_t)(rbase + r) * 64 + l];
            float4 xb = xg[(size_t)(rbase + r) * 64 + 32 + l];
            accA.x = fmaf(xa.x, wv, accA.x); accA.y = fmaf(xa.y, wv, accA.y);
            accA.z = fmaf(xa.z, wv, accA.z); accA.w = fmaf(xa.w, wv, accA.w);
            accB.x = fmaf(xb.x, wv, accB.x); accB.y = fmaf(xb.y, wv, accB.y);
            accB.z = fmaf(xb.z, wv, accB.z); accB.w = fmaf(xb.w, wv, accB.w);
        }
        {
            float* o = &out[curb * HID + l * 4];
            atomicAdd(o + 0, accA.x); atomicAdd(o + 1, accA.y);
            atomicAdd(o + 2, accA.z); atomicAdd(o + 3, accA.w);
            float* o2 = o + 128;
            atomicAdd(o2 + 0, accB.x); atomicAdd(o2 + 1, accB.y);
            atomicAdd(o2 + 2, accB.z); atomicAdd(o2 + 3, accB.w);
            if (l == 0) atomicAdd(&g_sw[curb], wsum);
        }
    }
}

// ---------------- normalize: out[b][h] /= S[b] ----------------
__global__ void norm_kernel(float* __restrict__ out) {
    int i = blockIdx.x * blockDim.x + threadIdx.x;   // 0..262143
    float s = g_sw[i >> 8];
    float inv = (s > 0.f) ? __fdividef(1.f, s) : 0.f;
    out[i] *= inv;
}

extern "C" void kernel_launch(void* const* d_in, const int* in_sizes, int n_in,
                              void* d_out, int out_size) {
    const float* x     = (const float*)d_in[0];
    const int*   batch = (const int*)d_in[1];
    const float* W1    = (const float*)d_in[2];
    const float* b1    = (const float*)d_in[3];
    const float* W2    = (const float*)d_in[4];
    const float* b2    = (const float*)d_in[5];
    float* out = (float*)d_out;

    const int dyn = (A_OFF + 8 * A_WSZ) * 4;   // 131072 + 36864 = 167936 B
    cudaFuncSetAttribute(score_kernel, cudaFuncAttributeMaxDynamicSharedMemorySize, dyn);

    prep_kernel<<<32, 256>>>(W1);
    init_kernel<<<(NGRAPH * HID + 255) / 256, 256>>>(out);
    score_kernel<<<NSM, 256, dyn>>>(x, batch, b1, W2, b2, out);
    norm_kernel<<<NUM_NODES / HID / 4 * 4, 256>>>(out);
}

// round 10
// speedup vs baseline: 2.0788x; 1.0977x over previous
#include <cuda_runtime.h>
#include <cuda_bf16.h>
#include <math.h>
#include <stdint.h>

#define NUM_NODES 262144
#define HID 256
#define NGRAPH 1024
#define NTILES (NUM_NODES / 128)   // 2048
#define NSM 148

// ---------------- scratch (static device globals) ----------------
__device__ float g_sw[NGRAPH];     // segment sum of exp(score)
// W1^T packed b-frag quads: [kstep 0..15][nt 0..15][lane 0..31][bh0,bh1,bl0,bl1]
__device__ uint32_t g_B[16 * 16 * 32 * 4];   // 32768 u32 = 128KB

__device__ __forceinline__ uint32_t smem_u32(const void* p) {
    uint32_t a;
    asm("{ .reg .u64 t; cvta.to.shared.u64 t, %1; cvt.u32.u64 %0, t; }" : "=r"(a) : "l"(p));
    return a;
}
__device__ __forceinline__ void mma_bf16(float* c, const uint32_t* a,
                                         uint32_t b0, uint32_t b1) {
    asm volatile(
        "mma.sync.aligned.m16n8k16.row.col.f32.bf16.bf16.f32 "
        "{%0,%1,%2,%3}, {%4,%5,%6,%7}, {%8,%9}, {%0,%1,%2,%3};"
        : "+f"(c[0]), "+f"(c[1]), "+f"(c[2]), "+f"(c[3])
        : "r"(a[0]), "r"(a[1]), "r"(a[2]), "r"(a[3]), "r"(b0), "r"(b1));
}
__device__ __forceinline__ void ldsm_x4(uint32_t* a, uint32_t addr) {
    asm volatile("ldmatrix.sync.aligned.m8n8.x4.shared.b16 {%0,%1,%2,%3}, [%4];"
        : "=r"(a[0]), "=r"(a[1]), "=r"(a[2]), "=r"(a[3]) : "r"(addr));
}
__device__ __forceinline__ float tanh_fast(float h) {
    float t;
    asm("tanh.approx.f32 %0, %1;" : "=f"(t) : "f"(h));
    return t;
}

// ---------------- prep: W1^T -> packed split-bf16 b-frag quads -------------
__global__ void prep_kernel(const float* __restrict__ W1) {  // W1[256][128]
    int i = blockIdx.x * 256 + threadIdx.x;   // 0..8191
    if (i >= 8192) return;
    int l = i & 31, nt = (i >> 5) & 15, ks = i >> 9;
    int gr = l >> 2, qc = l & 3;
    int n = nt * 8 + gr;
    int kp0 = (ks >> 2) * 32 + (ks & 3) * 8 + qc;
    int kp1 = kp0 + 4;
    float w00 = W1[(2 * kp0) * 128 + n],     w01 = W1[(2 * kp0 + 1) * 128 + n];
    float w10 = W1[(2 * kp1) * 128 + n],     w11 = W1[(2 * kp1 + 1) * 128 + n];
    __nv_bfloat16 h00 = __float2bfloat16(w00), h01 = __float2bfloat16(w01);
    __nv_bfloat16 h10 = __float2bfloat16(w10), h11 = __float2bfloat16(w11);
    __nv_bfloat16 l00 = __float2bfloat16(w00 - __bfloat162float(h00));
    __nv_bfloat16 l01 = __float2bfloat16(w01 - __bfloat162float(h01));
    __nv_bfloat16 l10 = __float2bfloat16(w10 - __bfloat162float(h10));
    __nv_bfloat16 l11 = __float2bfloat16(w11 - __bfloat162float(h11));
    uint32_t* dst = g_B + i * 4;
    dst[0] = (uint32_t)*(unsigned short*)&h00 | ((uint32_t)*(unsigned short*)&h01 << 16);
    dst[1] = (uint32_t)*(unsigned short*)&h10 | ((uint32_t)*(unsigned short*)&h11 << 16);
    dst[2] = (uint32_t)*(unsigned short*)&l00 | ((uint32_t)*(unsigned short*)&l01 << 16);
    dst[3] = (uint32_t)*(unsigned short*)&l10 | ((uint32_t)*(unsigned short*)&l11 << 16);
}

__global__ void init_kernel(float* __restrict__ out) {
    int i = blockIdx.x * blockDim.x + threadIdx.x;
    if (i < NGRAPH * HID) out[i] = 0.f;
    if (i < NGRAPH) g_sw[i] = 0.f;
}

// ---------------------------------------------------------------------------
// fused score+pool (R9 structure). Inner-loop deltas: ldmatrix.x4 A loads,
// STS.64 A stores, tanh.approx epilogue.
// dyn smem u32: B quads [0, 32768) ; A slabs: warp w at 32768 + w*1152
// (hi [16][36], lo +576).
// ---------------------------------------------------------------------------
#define A_OFF 32768
#define A_WSZ 1152
#define A_PAD 36

__global__ void __launch_bounds__(256, 1) score_kernel(
    const float* __restrict__ x,
    const int* __restrict__ batch,
    const float* __restrict__ b1,
    const float* __restrict__ W2,
    const float* __restrict__ b2,
    float* __restrict__ out)
{
    extern __shared__ uint32_t sm[];
    __shared__ float sb1[128], sW2[128];

    const int tid = threadIdx.x, w = tid >> 5, l = tid & 31;
    const int gr = l >> 2, qc = l & 3;

    {   // B copy: 32768 u32 = 8192 float4
        const float4* src = (const float4*)g_B;
        float4* dst = (float4*)sm;
        #pragma unroll
        for (int i = 0; i < 32; ++i) dst[tid + i * 256] = src[tid + i * 256];
    }
    if (tid < 128) { sb1[tid] = b1[tid]; sW2[tid] = W2[tid]; }
    __syncthreads();

    const float b2v = __ldg(&b2[0]);
    uint32_t* const Ahi = sm + A_OFF + w * A_WSZ;
    uint32_t* const Alo = Ahi + 576;
    // ldmatrix per-lane address: lanes 0-15 -> rows 0-15 (k-group 0),
    // lanes 16-31 -> rows 0-15 (k-group 1, +4 u32)
    const uint32_t a_hi_base = smem_u32(Ahi) + ((l & 15) * A_PAD + (l >> 4) * 4) * 4;
    const uint32_t a_lo_base = a_hi_base + 576 * 4;
    const uint4* const Bq = (const uint4*)sm;     // [kstep][nt][lane]
    const float4* xg = (const float4*)x;          // [node][64]

    for (int t = blockIdx.x; t < NTILES; t += NSM) {
        const int rbase = t * 128 + w * 16;

        float acc[16][4];
        #pragma unroll
        for (int nt = 0; nt < 16; ++nt)
            #pragma unroll
            for (int j = 0; j < 4; ++j) acc[nt][j] = 0.f;

        float4 v[8];
        #pragma unroll
        for (int i = 0; i < 8; ++i) {
            int f = i * 32 + l;
            v[i] = xg[(size_t)(rbase + (f >> 4)) * 64 + (f & 15)];
        }

        for (int c = 0; c < 4; ++c) {
            __syncwarp();
            #pragma unroll
            for (int i = 0; i < 8; ++i) {
                int f = i * 32 + l;
                int r = f >> 4, q = f & 15;
                __nv_bfloat162 h01 = __float22bfloat162_rn(make_float2(v[i].x, v[i].y));
                __nv_bfloat162 h23 = __float22bfloat162_rn(make_float2(v[i].z, v[i].w));
                float2 f01 = __bfloat1622float2(h01);
                float2 f23 = __bfloat1622float2(h23);
                __nv_bfloat162 l01 = __float22bfloat162_rn(make_float2(v[i].x - f01.x, v[i].y - f01.y));
                __nv_bfloat162 l23 = __float22bfloat162_rn(make_float2(v[i].z - f23.x, v[i].w - f23.y));
                uint64_t hv = (uint64_t)(*(uint32_t*)&h01) | ((uint64_t)(*(uint32_t*)&h23) << 32);
                uint64_t lv = (uint64_t)(*(uint32_t*)&l01) | ((uint64_t)(*(uint32_t*)&l23) << 32);
                *(uint64_t*)(Ahi + r * A_PAD + q * 2) = hv;   // STS.64
                *(uint64_t*)(Alo + r * A_PAD + q * 2) = lv;
            }
            __syncwarp();
            if (c < 3) {
                #pragma unroll
                for (int i = 0; i < 8; ++i) {
                    int f = i * 32 + l;
                    v[i] = xg[(size_t)(rbase + (f >> 4)) * 64 + (c + 1) * 16 + (f & 15)];
                }
            }
            for (int k16 = 0; k16 < 4; ++k16) {
                uint32_t ah[4], al[4];
                ldsm_x4(ah, a_hi_base + k16 * 32);
                ldsm_x4(al, a_lo_base + k16 * 32);
                const uint4* Bk = Bq + ((c * 4 + k16) * 16) * 32 + l;
                #pragma unroll
                for (int nt = 0; nt < 16; ++nt) {
                    uint4 q = Bk[nt * 32];          // LDS.128, conflict-free
                    mma_bf16(acc[nt], ah, q.x, q.y);
                    mma_bf16(acc[nt], ah, q.z, q.w);
                    mma_bf16(acc[nt], al, q.x, q.y);
                }
            }
        }

        // epilogue: row scores via HW tanh. All 4 quad lanes end with p0/p1.
        float p0 = 0.f, p1 = 0.f;
        #pragma unroll
        for (int nt = 0; nt < 16; ++nt) {
            #pragma unroll
            for (int j = 0; j < 2; ++j) {
                int col = nt * 8 + qc * 2 + j;
                float bb = sb1[col], ww = sW2[col];
                p0 = fmaf(tanh_fast(acc[nt][j] + bb), ww, p0);
                p1 = fmaf(tanh_fast(acc[nt][2 + j] + bb), ww, p1);
            }
        }
        p0 += __shfl_xor_sync(0xFFFFFFFFu, p0, 1);
        p0 += __shfl_xor_sync(0xFFFFFFFFu, p0, 2);
        p1 += __shfl_xor_sync(0xFFFFFFFFu, p1, 1);
        p1 += __shfl_xor_sync(0xFFFFFFFFu, p1, 2);

        // ---- fused pool phase: re-read 16 rows x 256 cols (L2-hot) ----
        float4 accA = make_float4(0.f, 0.f, 0.f, 0.f);
        float4 accB = make_float4(0.f, 0.f, 0.f, 0.f);
        float wsum = 0.f;
        int curb = __ldg(&batch[rbase]);
        #pragma unroll
        for (int r = 0; r < 16; ++r) {
            float sc = (r < 8) ? __shfl_sync(0xFFFFFFFFu, p0, r * 4)
                               : __shfl_sync(0xFFFFFFFFu, p1, (r - 8) * 4);
            float wv = __expf(sc + b2v);
            int b = __ldg(&batch[rbase + r]);
            if (b != curb) {
                float* o = &out[curb * HID + l * 4];
                atomicAdd(o + 0, accA.x); atomicAdd(o + 1, accA.y);
                atomicAdd(o + 2, accA.z); atomicAdd(o + 3, accA.w);
                float* o2 = o + 128;
                atomicAdd(o2 + 0, accB.x); atomicAdd(o2 + 1, accB.y);
                atomicAdd(o2 + 2, accB.z); atomicAdd(o2 + 3, accB.w);
                if (l == 0) atomicAdd(&g_sw[curb], wsum);
                accA = make_float4(0.f, 0.f, 0.f, 0.f);
                accB = make_float4(0.f, 0.f, 0.f, 0.f);
                wsum = 0.f;
                curb = b;
            }
            wsum += wv;
            float4 xa = xg[(size_t)(rbase + r) * 64 + l];
            float4 xb = xg[(size_t)(rbase + r) * 64 + 32 + l];
            accA.x = fmaf(xa.x, wv, accA.x); accA.y = fmaf(xa.y, wv, accA.y);
            accA.z = fmaf(xa.z, wv, accA.z); accA.w = fmaf(xa.w, wv, accA.w);
            accB.x = fmaf(xb.x, wv, accB.x); accB.y = fmaf(xb.y, wv, accB.y);
            accB.z = fmaf(xb.z, wv, accB.z); accB.w = fmaf(xb.w, wv, accB.w);
        }
        {
            float* o = &out[curb * HID + l * 4];
            atomicAdd(o + 0, accA.x); atomicAdd(o + 1, accA.y);
            atomicAdd(o + 2, accA.z); atomicAdd(o + 3, accA.w);
            float* o2 = o + 128;
            atomicAdd(o2 + 0, accB.x); atomicAdd(o2 + 1, accB.y);
            atomicAdd(o2 + 2, accB.z); atomicAdd(o2 + 3, accB.w);
            if (l == 0) atomicAdd(&g_sw[curb], wsum);
        }
    }
}

// ---------------- normalize: out[b][h] /= S[b] ----------------
__global__ void norm_kernel(float* __restrict__ out) {
    int i = blockIdx.x * blockDim.x + threadIdx.x;   // 0..262143
    float s = g_sw[i >> 8];
    float inv = (s > 0.f) ? __fdividef(1.f, s) : 0.f;
    out[i] *= inv;
}

extern "C" void kernel_launch(void* const* d_in, const int* in_sizes, int n_in,
                              void* d_out, int out_size) {
    const float* x     = (const float*)d_in[0];
    const int*   batch = (const int*)d_in[1];
    const float* W1    = (const float*)d_in[2];
    const float* b1    = (const float*)d_in[3];
    const float* W2    = (const float*)d_in[4];
    const float* b2    = (const float*)d_in[5];
    float* out = (float*)d_out;

    const int dyn = (A_OFF + 8 * A_WSZ) * 4;   // 131072 + 36864 = 167936 B
    cudaFuncSetAttribute(score_kernel, cudaFuncAttributeMaxDynamicSharedMemorySize, dyn);

    prep_kernel<<<32, 256>>>(W1);
    init_kernel<<<(NGRAPH * HID + 255) / 256, 256>>>(out);
    score_kernel<<<NSM, 256, dyn>>>(x, batch, b1, W2, b2, out);
    norm_kernel<<<NGRAPH * HID / 256, 256>>>(out);
}